// round 16
// baseline (speedup 1.0000x reference)
#include <cuda_runtime.h>

// Sinkhorn distance, N=M=4096, D=2, P=1, eps=0.1, 50 iterations.
// R14 skeleton (best, 817us): 128 CTAs x 1024 thr, warp-local staging,
// transposed conflict-free reduce, atomicAdd+volatile-spin barrier.
// CHANGE vs R14: inner step is pure SCALAR FADD/EX2 with -|.| operand
// modifiers (no f32x2, no pack/unpack MOVs). Same memory layout.

#define NN      4096
#define NCTA    128
#define NT      1024
#define NWARP   32
#define RPC     32          // rows (or cols) owned per CTA
#define PPW     64          // float2-pairs per warp per pass
#define ITERS   50

#define SCALEF      14.426950408889634f    // log2(e)/eps
#define INV_SCALEF  0.06931471805599453f   // eps*ln(2)
#define LMU2        (-11.9999409054f)      // log2(1/4096 + 1e-8)

__device__ __align__(256) float g_u[NN];
__device__ __align__(256) float g_v[NN];
__device__ float g_cost[NCTA];
__device__ unsigned int g_costcnt;
__device__ unsigned int sk_bar_count;
__device__ volatile unsigned int sk_bar_phase;

__device__ __forceinline__ float ex2f(float v) {
    float r; asm("ex2.approx.f32 %0, %1;" : "=f"(r) : "f"(v)); return r;
}
__device__ __forceinline__ float lg2f(float v) {
    float r; asm("lg2.approx.f32 %0, %1;" : "=f"(r) : "f"(v)); return r;
}

// Proven barrier: atomicAdd arrival, tid0 spins on one volatile word.
__device__ __forceinline__ void grid_barrier(unsigned int target) {
    __threadfence();
    __syncthreads();
    if (threadIdx.x == 0) {
        unsigned int t = atomicAdd(&sk_bar_count, 1u);
        if (t == NCTA - 1) {
            sk_bar_count = 0;
            __threadfence();
            sk_bar_phase = target;
        } else {
            while (sk_bar_phase < target) { }
        }
    }
    __syncthreads();
}

__global__ void sk_init_kernel() {
    int t = blockIdx.x * blockDim.x + threadIdx.x;
    if (t == 0) { sk_bar_count = 0; sk_bar_phase = 0; g_costcnt = 0; }
    for (int i = t; i < NN; i += gridDim.x * blockDim.x) g_v[i] = 0.f;
}

// Scalar 2-element step. c = {-y0a, -y0b, -y1a, -y1b} (negated, pre-scaled).
// acc_a += 2^{va - |X0-y0a| - |X1-y1a|}; acc_b += same for b.
__device__ __forceinline__ void sk_step2(float& accA, float& accB, float4 c,
                                         float va, float vb, float X0, float X1) {
    float d0a = X0 + c.x;
    float d1a = X1 + c.z;
    float d0b = X0 + c.y;
    float d1b = X1 + c.w;
    float ta = -fabsf(d0a) - fabsf(d1a);   // FADD with -|.| operand modifiers
    float tb = -fabsf(d0b) - fabsf(d1b);
    accA += ex2f(va + ta);
    accB += ex2f(vb + tb);
}

// Warp-level pass body: stage own 128-float slice of `gvec`, then sum over it.
__device__ __forceinline__ float warp_pass(const float4* __restrict__ cb,
                                           float* __restrict__ svec,
                                           const float* __restrict__ gvec,
                                           int wid, int lane, float X0, float X1) {
    const int c4 = wid * 32 + lane;
    ((float4*)svec)[c4] = __ldcg(((const float4*)gvec) + c4);
    __syncwarp();

    const float4* vb4 = (const float4*)svec + wid * 32;   // 32 float4 = 64 pairs
    float a0 = 0.f, a1 = 0.f, a2 = 0.f, a3 = 0.f;
    float a4 = 0.f, a5 = 0.f, a6 = 0.f, a7 = 0.f;
    #pragma unroll 4
    for (int k = 0; k < 32; k += 2) {
        float4 c0 = cb[2 * k + 0];
        float4 c1 = cb[2 * k + 1];
        float4 v0 = vb4[k];
        sk_step2(a0, a1, c0, v0.x, v0.y, X0, X1);
        sk_step2(a2, a3, c1, v0.z, v0.w, X0, X1);
        float4 c2 = cb[2 * k + 2];
        float4 c3 = cb[2 * k + 3];
        float4 v1 = vb4[k + 1];
        sk_step2(a4, a5, c2, v1.x, v1.y, X0, X1);
        sk_step2(a6, a7, c3, v1.z, v1.w, X0, X1);
    }
    return ((a0 + a1) + (a2 + a3)) + ((a4 + a5) + (a6 + a7));
}

__global__ void __launch_bounds__(NT, 1)
sk_persist_kernel(const float* __restrict__ x, const float* __restrict__ y,
                  float* __restrict__ out) {
    extern __shared__ float4 smem_raw[];
    float4* sxc = smem_raw;                 // 32KB {-x0a,-x0b,-x1a,-x1b} pair-interleaved
    float4* syc = smem_raw + NN / 2;        // 32KB
    float*  su  = (float*)(smem_raw + NN);  // 16KB
    float*  sv  = su + NN;                  // 16KB
    __shared__ float part[NWARP * 33];
    __shared__ float red[NWARP];

    const int tid  = threadIdx.x;
    const int lane = tid & 31;
    const int wid  = tid >> 5;
    const int cta  = blockIdx.x;
    const int rbase = cta * RPC;

    // Prologue: negated, pre-scaled coords (immutable).
    for (int p = tid; p < NN / 2; p += NT) {
        float4 r = ((const float4*)x)[p];
        sxc[p] = make_float4(-SCALEF * r.x, -SCALEF * r.z, -SCALEF * r.y, -SCALEF * r.w);
        float4 q = ((const float4*)y)[p];
        syc[p] = make_float4(-SCALEF * q.x, -SCALEF * q.z, -SCALEF * q.y, -SCALEF * q.w);
    }
    __syncthreads();

    const int myrow = rbase + lane;
    const float X0 = x[2 * myrow] * SCALEF;
    const float X1 = x[2 * myrow + 1] * SCALEF;
    const float Y0 = y[2 * myrow] * SCALEF;
    const float Y1 = y[2 * myrow + 1] * SCALEF;

    unsigned int phase = 0;

    for (int it = 0; it < ITERS; ++it) {
        // ===== u pass: u_i = LMU2 - log2( sum_j 2^{v_j - C_ij} ) =====
        part[wid * 33 + lane] = warp_pass(syc + wid * PPW, sv, g_v, wid, lane, X0, X1);
        __syncthreads();
        {   // warp `wid` reduces row rbase+wid (transposed, conflict-free)
            float pv = part[lane * 33 + wid];
            #pragma unroll
            for (int o = 16; o > 0; o >>= 1) pv += __shfl_xor_sync(0xffffffffu, pv, o);
            if (lane == 0) __stcg(&g_u[rbase + wid], LMU2 - lg2f(pv));
        }
        grid_barrier(++phase);

        // ===== v pass: v_j = LMU2 - log2( sum_i 2^{u_i - C_ij} ) =====
        part[wid * 33 + lane] = warp_pass(sxc + wid * PPW, su, g_u, wid, lane, Y0, Y1);
        __syncthreads();
        {
            float pv = part[lane * 33 + wid];
            #pragma unroll
            for (int o = 16; o > 0; o >>= 1) pv += __shfl_xor_sync(0xffffffffu, pv, o);
            if (lane == 0) __stcg(&g_v[rbase + wid], LMU2 - lg2f(pv));
        }
        grid_barrier(++phase);
    }

    // ===== final: pi = 2^{u_i + v_j - C_ij}, C, cost = sum(pi*C) =====
    ((float4*)sv)[tid] = __ldcg((const float4*)g_v + tid);
    ((float4*)su)[tid] = __ldcg((const float4*)g_u + tid);
    __syncthreads();

    const size_t NM = (size_t)NN * NN;
    float* pi_out = out + 1;
    float* c_out  = out + 1 + NM;

    float cacc = 0.f;
    for (int r = 0; r < RPC; ++r) {
        const int i = rbase + r;
        const float Xa = x[2 * i] * SCALEF;
        const float Xb = x[2 * i + 1] * SCALEF;
        const float ui = su[i];
        const size_t off = (size_t)i * NN;
        for (int q = tid; q < NN / 4; q += NT) {
            float4 ca = syc[2 * q];
            float4 cb = syc[2 * q + 1];
            float4 v4 = ((const float4*)sv)[q];
            float ct0 = fabsf(Xa + ca.x) + fabsf(Xb + ca.z);
            float ct1 = fabsf(Xa + ca.y) + fabsf(Xb + ca.w);
            float ct2 = fabsf(Xa + cb.x) + fabsf(Xb + cb.z);
            float ct3 = fabsf(Xa + cb.y) + fabsf(Xb + cb.w);
            float p0 = ex2f(ui + v4.x - ct0);
            float p1 = ex2f(ui + v4.y - ct1);
            float p2 = ex2f(ui + v4.z - ct2);
            float p3 = ex2f(ui + v4.w - ct3);
            float c0 = ct0 * INV_SCALEF, c1 = ct1 * INV_SCALEF;
            float c2 = ct2 * INV_SCALEF, c3 = ct3 * INV_SCALEF;
            const size_t b = off + 4 * (size_t)q;
            pi_out[b + 0] = p0; pi_out[b + 1] = p1; pi_out[b + 2] = p2; pi_out[b + 3] = p3;
            c_out[b + 0]  = c0; c_out[b + 1]  = c1; c_out[b + 2]  = c2; c_out[b + 3]  = c3;
            cacc += p0 * c0 + p1 * c1;
            cacc += p2 * c2 + p3 * c3;
        }
    }
    #pragma unroll
    for (int o = 16; o > 0; o >>= 1) cacc += __shfl_xor_sync(0xffffffffu, cacc, o);
    if (lane == 0) red[wid] = cacc;
    __syncthreads();
    if (wid == 0) {
        float s = red[lane];
        #pragma unroll
        for (int o = 16; o > 0; o >>= 1) s += __shfl_xor_sync(0xffffffffu, s, o);
        if (lane == 0) {
            __stcg(&g_cost[cta], s);
            __threadfence();
            unsigned int old = atomicAdd(&g_costcnt, 1u);
            if (old == NCTA - 1) {          // last CTA: deterministic final sum
                __threadfence();
                float t = 0.f;
                for (int b = 0; b < NCTA; ++b) t += __ldcg(&g_cost[b]);
                out[0] = t;                 // cost ** (1/P), P = 1
            }
        }
    }
}

extern "C" void kernel_launch(void* const* d_in, const int* in_sizes, int n_in,
                              void* d_out, int out_size) {
    (void)in_sizes; (void)n_in; (void)out_size;
    const float* x = (const float*)d_in[0];
    const float* y = (const float*)d_in[1];
    float* out = (float*)d_out;

    const size_t smem = (size_t)NN * sizeof(float4) + 2 * NN * sizeof(float); // 96KB
    cudaFuncSetAttribute(sk_persist_kernel,
                         cudaFuncAttributeMaxDynamicSharedMemorySize, (int)smem);

    sk_init_kernel<<<8, 512>>>();
    sk_persist_kernel<<<NCTA, NT, smem>>>(x, y, out);
}